// round 1
// baseline (speedup 1.0000x reference)
#include <cuda_runtime.h>

#define Bsz 8
#define FD 1024
#define Hh 256
#define NN 65536            // N*N per batch
#define BNN (Bsz*NN)        // 524288
#define Ksel 39321          // int(0.6 * 65536)
#define M_TOT 2048          // B*N
#define J_TOT 512           // 2H

// ---------------- scratch (no allocations allowed) ----------------
__device__ float    g_pp[M_TOT * J_TOT];   // [m][0:256)=pr+b1, [256:512)=pc  (4 MB)
__device__ float    g_e[BNN];              // unnormalized exp                 (2 MB)
__device__ unsigned g_maxkey[Bsz];
__device__ float    g_inv_denom[Bsz];
__device__ float    g_part[Bsz * 64];
__device__ float    g_thr[Bsz];
__device__ float    g_cpart[Bsz * 64];
__device__ float    g_inv_csum[Bsz];

// monotone float<->uint encoding (for atomicMax over possibly-negative floats)
__device__ __forceinline__ unsigned encf(float f) {
    unsigned u = __float_as_uint(f);
    return (u & 0x80000000u) ? ~u : (u | 0x80000000u);
}
__device__ __forceinline__ float decf(unsigned u) {
    unsigned v = (u & 0x80000000u) ? (u ^ 0x80000000u) : ~u;
    return __uint_as_float(v);
}

__global__ void init_kernel() {
    if (threadIdx.x < Bsz) g_maxkey[threadIdx.x] = 0u;  // enc(-inf) < 0u for all reals
}

// ---------------- 1) GEMM: C[m][j] = sum_f x[m][f] * Bmat[j][f] ----------------
// Bmat[j][f] = W1[(j&255)][(j>>8)*1024 + f]   (j<256 -> pr weights, j>=256 -> pc)
// epilogue folds b1 into cols < 256.
__global__ __launch_bounds__(256) void gemm_kernel(
    const float* __restrict__ x, const float* __restrict__ W1, const float* __restrict__ b1)
{
    __shared__ float As[16][68];
    __shared__ float Bs[16][68];
    const int tid = threadIdx.x;
    const int m0 = blockIdx.y << 6;
    const int j0 = blockIdx.x << 6;
    const int tx = tid & 15, ty = tid >> 4;
    const int lr = tid >> 2;            // 0..63
    const int lc = (tid & 3) << 2;      // 0,4,8,12
    const int jrow = j0 + lr;
    const float* wrow = W1 + (jrow & 255) * 2048 + (jrow >> 8) * 1024;
    const float* arow = x + (m0 + lr) * 1024;
    float acc[4][4] = {};
    for (int k0 = 0; k0 < FD; k0 += 16) {
        float4 av = *(const float4*)(arow + k0 + lc);
        float4 bv = *(const float4*)(wrow + k0 + lc);
        __syncthreads();
        As[lc + 0][lr] = av.x; As[lc + 1][lr] = av.y; As[lc + 2][lr] = av.z; As[lc + 3][lr] = av.w;
        Bs[lc + 0][lr] = bv.x; Bs[lc + 1][lr] = bv.y; Bs[lc + 2][lr] = bv.z; Bs[lc + 3][lr] = bv.w;
        __syncthreads();
        #pragma unroll
        for (int k = 0; k < 16; k++) {
            float a[4], bb[4];
            *(float4*)a  = *(const float4*)&As[k][ty << 2];
            *(float4*)bb = *(const float4*)&Bs[k][tx << 2];
            #pragma unroll
            for (int i = 0; i < 4; i++)
                #pragma unroll
                for (int j = 0; j < 4; j++)
                    acc[i][j] = fmaf(a[i], bb[j], acc[i][j]);
        }
    }
    #pragma unroll
    for (int i = 0; i < 4; i++) {
        int m = m0 + (ty << 2) + i;
        #pragma unroll
        for (int j = 0; j < 4; j++) {
            int col = j0 + (tx << 2) + j;
            float v = acc[i][j];
            if (col < 256) v += b1[col];
            g_pp[m * 512 + col] = v;
        }
    }
}

// ---------------- 2) edge[b,i,j] = sum_h relu(pr[i,h]+pc[j,h])*w2[h] + b2 ----------------
__global__ __launch_bounds__(256) void edge_kernel(
    const float* __restrict__ W2, const float* __restrict__ b2, float* __restrict__ out_edge)
{
    __shared__ float prs[64][33];
    __shared__ float pcs[64][33];
    __shared__ float w2s[32];
    __shared__ float redbuf[8];
    const int b  = blockIdx.z;
    const int i0 = blockIdx.y << 6;
    const int j0 = blockIdx.x << 6;
    const int tid = threadIdx.x;
    const int tx = tid & 15, ty = tid >> 4;
    const float* base = g_pp + (b << 8) * 512;
    float acc[4][4] = {};
    for (int hc = 0; hc < 256; hc += 32) {
        __syncthreads();
        #pragma unroll
        for (int t = 0; t < 2; t++) {
            int idx = tid + (t << 8);            // 0..511 float4 slots
            int r = idx >> 3;
            int hv = (idx & 7) << 2;
            float4 v = *(const float4*)(base + (i0 + r) * 512 + hc + hv);
            prs[r][hv] = v.x; prs[r][hv + 1] = v.y; prs[r][hv + 2] = v.z; prs[r][hv + 3] = v.w;
            float4 u = *(const float4*)(base + (j0 + r) * 512 + 256 + hc + hv);
            pcs[r][hv] = u.x; pcs[r][hv + 1] = u.y; pcs[r][hv + 2] = u.z; pcs[r][hv + 3] = u.w;
        }
        if (tid < 32) w2s[tid] = W2[hc + tid];
        __syncthreads();
        #pragma unroll
        for (int h = 0; h < 32; h++) {
            float w = w2s[h];
            float a[4], c[4];
            #pragma unroll
            for (int t = 0; t < 4; t++) { a[t] = prs[(ty << 2) + t][h]; c[t] = pcs[(tx << 2) + t][h]; }
            #pragma unroll
            for (int i = 0; i < 4; i++)
                #pragma unroll
                for (int j = 0; j < 4; j++) {
                    float v = a[i] + c[j];
                    v = fmaxf(v, 0.f);
                    acc[i][j] = fmaf(v, w, acc[i][j]);
                }
        }
    }
    float bb = b2[0];
    float lmax = -3.4e38f;
    #pragma unroll
    for (int i = 0; i < 4; i++) {
        int ii = i0 + (ty << 2) + i;
        #pragma unroll
        for (int j = 0; j < 4; j++) {
            int jj = j0 + (tx << 2) + j;
            float e = acc[i][j] + bb;
            out_edge[(b << 16) + (ii << 8) + jj] = e;
            lmax = fmaxf(lmax, e);
        }
    }
    #pragma unroll
    for (int o = 16; o > 0; o >>= 1) lmax = fmaxf(lmax, __shfl_xor_sync(0xffffffffu, lmax, o));
    if ((tid & 31) == 0) redbuf[tid >> 5] = lmax;
    __syncthreads();
    if (tid == 0) {
        float m = redbuf[0];
        #pragma unroll
        for (int i = 1; i < 8; i++) m = fmaxf(m, redbuf[i]);
        atomicMax(&g_maxkey[b], encf(m));
    }
}

// ---------------- 3) exp + deterministic partial sums ----------------
__global__ __launch_bounds__(256) void exp_kernel(const float* __restrict__ edge)
{
    const int b = blockIdx.y;
    const int blk = blockIdx.x;     // 0..63
    const int tid = threadIdx.x;
    __shared__ float red[8];
    const float smax = 2.0f * decf(g_maxkey[b]);   // s = edge/TEMP = edge*2
    const int base = (b << 16) + (blk << 10);
    float s = 0.f;
    #pragma unroll
    for (int t = 0; t < 4; t++) {
        int idx = base + (t << 8) + tid;
        float e2 = __expf(fmaf(edge[idx], 2.0f, -smax));
        g_e[idx] = e2;
        s += e2;
    }
    #pragma unroll
    for (int o = 16; o > 0; o >>= 1) s += __shfl_xor_sync(0xffffffffu, s, o);
    if ((tid & 31) == 0) red[tid >> 5] = s;
    __syncthreads();
    if (tid == 0) {
        float tot = 0.f;
        #pragma unroll
        for (int i = 0; i < 8; i++) tot += red[i];
        g_part[(b << 6) + blk] = tot;
    }
}

__global__ void denom_kernel() {
    const int b = blockIdx.x, tid = threadIdx.x;   // 64 threads
    __shared__ float r2[2];
    float v = g_part[(b << 6) + tid];
    #pragma unroll
    for (int o = 16; o > 0; o >>= 1) v += __shfl_xor_sync(0xffffffffu, v, o);
    if ((tid & 31) == 0) r2[tid >> 5] = v;
    __syncthreads();
    if (tid == 0) g_inv_denom[b] = 1.0f / (r2[0] + r2[1]);
}

__global__ void soft_kernel(float* __restrict__ out_soft) {
    int idx = blockIdx.x * 256 + threadIdx.x;
    out_soft[idx] = g_e[idx] * g_inv_denom[idx >> 16];
}

// ---------------- 4) radix select: k-th largest soft per batch ----------------
__global__ __launch_bounds__(1024) void select_kernel(const float* __restrict__ soft)
{
    __shared__ unsigned hist[8][256];
    __shared__ unsigned sh_prefix;
    __shared__ int sh_rem;
    const int b = blockIdx.x;
    const int tid = threadIdx.x;
    const unsigned* keys = (const unsigned*)(soft + (b << 16));   // all positive floats
    if (tid == 0) { sh_rem = Ksel; sh_prefix = 0u; }
    unsigned mask = 0u;
    for (int byte = 3; byte >= 0; byte--) {
        for (int i = tid; i < 2048; i += 1024) ((unsigned*)hist)[i] = 0u;
        __syncthreads();
        const unsigned prefix = sh_prefix;
        const int wg = (tid >> 5) & 7;
        const int sh = byte << 3;
        for (int t = tid; t < NN; t += 1024) {
            unsigned key = keys[t];
            if ((key & mask) == prefix)
                atomicAdd(&hist[wg][(key >> sh) & 255u], 1u);
        }
        __syncthreads();
        if (tid < 256) {
            unsigned s = 0;
            #pragma unroll
            for (int c = 0; c < 8; c++) s += hist[c][tid];
            hist[0][tid] = s;
        }
        __syncthreads();
        if (tid == 0) {
            int rem = sh_rem;
            unsigned cum = 0;
            int sel = 0;
            for (int bb = 255; bb >= 0; bb--) {
                unsigned c = hist[0][bb];
                if (cum + c >= (unsigned)rem) { sel = bb; sh_rem = rem - (int)cum; break; }
                cum += c;
            }
            sh_prefix = prefix | ((unsigned)sel << sh);
        }
        __syncthreads();
        mask |= (255u << sh);
    }
    if (tid == 0) g_thr[b] = __uint_as_float(sh_prefix);
}

// ---------------- 5) masked sum + final write ----------------
__global__ __launch_bounds__(256) void cmask_sum_kernel(const float* __restrict__ soft)
{
    const int b = blockIdx.y, blk = blockIdx.x, tid = threadIdx.x;
    __shared__ float red[8];
    const float thr = g_thr[b];
    const int base = (b << 16) + (blk << 10);
    float s = 0.f;
    #pragma unroll
    for (int t = 0; t < 4; t++) {
        float v = soft[base + (t << 8) + tid];
        if (v >= thr) s += v;
    }
    #pragma unroll
    for (int o = 16; o > 0; o >>= 1) s += __shfl_xor_sync(0xffffffffu, s, o);
    if ((tid & 31) == 0) red[tid >> 5] = s;
    __syncthreads();
    if (tid == 0) {
        float tot = 0.f;
        #pragma unroll
        for (int i = 0; i < 8; i++) tot += red[i];
        g_cpart[(b << 6) + blk] = tot;
    }
}

__global__ void csum_final_kernel() {
    const int b = blockIdx.x, tid = threadIdx.x;   // 64 threads
    __shared__ float r2[2];
    float v = g_cpart[(b << 6) + tid];
    #pragma unroll
    for (int o = 16; o > 0; o >>= 1) v += __shfl_xor_sync(0xffffffffu, v, o);
    if ((tid & 31) == 0) r2[tid >> 5] = v;
    __syncthreads();
    if (tid == 0) g_inv_csum[b] = 1.0f / (r2[0] + r2[1] + 1e-12f);
}

__global__ void final_kernel(const float* __restrict__ soft,
                             float* __restrict__ out_causal, float* __restrict__ out_conf)
{
    int idx = blockIdx.x * 256 + threadIdx.x;
    int b = idx >> 16;
    float v = soft[idx];
    float c = (v >= g_thr[b]) ? v * g_inv_csum[b] : 0.f;
    out_causal[idx] = c;
    out_conf[idx] = 1.f - c;
}

// ---------------- launch ----------------
extern "C" void kernel_launch(void* const* d_in, const int* in_sizes, int n_in,
                              void* d_out, int out_size)
{
    const float* x  = (const float*)d_in[0];
    const float* W1 = (const float*)d_in[1];
    const float* b1 = (const float*)d_in[2];
    const float* W2 = (const float*)d_in[3];
    const float* b2 = (const float*)d_in[4];
    float* out = (float*)d_out;
    float* out_causal = out;
    float* out_conf   = out + BNN;
    float* out_edge   = out + 2 * BNN;
    float* out_soft   = out + 3 * BNN;

    init_kernel<<<1, 32>>>();
    gemm_kernel<<<dim3(8, 32), 256>>>(x, W1, b1);
    edge_kernel<<<dim3(4, 4, Bsz), 256>>>(W2, b2, out_edge);
    exp_kernel<<<dim3(64, Bsz), 256>>>(out_edge);
    denom_kernel<<<Bsz, 64>>>();
    soft_kernel<<<2048, 256>>>(out_soft);
    select_kernel<<<Bsz, 1024>>>(out_soft);
    cmask_sum_kernel<<<dim3(64, Bsz), 256>>>(out_soft);
    csum_final_kernel<<<Bsz, 64>>>();
    final_kernel<<<2048, 256>>>(out_soft, out_causal, out_conf);
}